// round 16
// baseline (speedup 1.0000x reference)
#include <cuda_runtime.h>
#include <cuda_bf16.h>
#include <cuda_fp16.h>
#include <cstdint>

#define NNODES 100000
#define DDIM 256
#define KH 4
#define RR 16
#define CDIM 64            // KH*RR
#define XDIM (DDIM + CDIM) // 320
#define EMAX 1700000
#define NBLK_SCAN 98       // ceil(NNODES/1024)

// -------- scratch --------
__device__ float g_ZU[NNODES * CDIM];
__device__ float g_agg[NNODES * CDIM];
__device__ float g_W[CDIM * DDIM];
__device__ float g_M1[DDIM * DDIM];
__device__ float g_M[DDIM * DDIM];
__device__ uint32_t g_UtH[CDIM * (DDIM / 2)];   // bf16 pairs (zu, 3-term)
__device__ uint32_t g_UtL[CDIM * (DDIM / 2)];
__device__ uint32_t g_GtF[DDIM * (XDIM / 2)];   // fp16 pairs [n][k-pair] (final, 2-term)
// CSR
__device__ int g_cnt[NNODES];
__device__ int g_off[NNODES + 1];
__device__ int g_cursor[NNODES];
__device__ int g_bsum[NBLK_SCAN];
__device__ int g_bpre[NBLK_SCAN];
__device__ int g_srcl[EMAX];

// -------- bf16 helpers (zu path) --------
__device__ __forceinline__ uint32_t pk(__nv_bfloat16 a, __nv_bfloat16 b) {
    __nv_bfloat162 t = __halves2bfloat162(a, b);
    return *(uint32_t*)&t;
}
__device__ __forceinline__ void bf_split(float x, __nv_bfloat16& h, __nv_bfloat16& l) {
    h = __float2bfloat16(x);
    l = __float2bfloat16(x - __bfloat162float(h));
}
__device__ __forceinline__ void split_pack4(float4 v, uint32_t& h01, uint32_t& h23,
                                            uint32_t& l01, uint32_t& l23) {
    __nv_bfloat16 hx, lx, hy, ly, hz, lz, hw, lw;
    bf_split(v.x, hx, lx); bf_split(v.y, hy, ly);
    bf_split(v.z, hz, lz); bf_split(v.w, hw, lw);
    h01 = pk(hx, hy); h23 = pk(hz, hw);
    l01 = pk(lx, ly); l23 = pk(lz, lw);
}
__device__ __forceinline__ void mma16(float* d, const uint32_t* a, const uint32_t* b) {
    asm volatile(
        "mma.sync.aligned.m16n8k16.row.col.f32.bf16.bf16.f32 "
        "{%0,%1,%2,%3},{%4,%5,%6,%7},{%8,%9},{%0,%1,%2,%3};"
        : "+f"(d[0]), "+f"(d[1]), "+f"(d[2]), "+f"(d[3])
        : "r"(a[0]), "r"(a[1]), "r"(a[2]), "r"(a[3]), "r"(b[0]), "r"(b[1]));
}

// -------- fp16 helpers (final path) --------
__device__ __forceinline__ uint32_t pkh(__half a, __half b) {
    __half2 t = __halves2half2(a, b);
    return *(uint32_t*)&t;
}
__device__ __forceinline__ void h_split(float x, __half& h, __half& l) {
    h = __float2half(x);
    l = __float2half(x - __half2float(h));
}
__device__ __forceinline__ void split_pack4h(float4 v, uint32_t& h01, uint32_t& h23,
                                             uint32_t& l01, uint32_t& l23) {
    __half hx, lx, hy, ly, hz, lz, hw, lw;
    h_split(v.x, hx, lx); h_split(v.y, hy, ly);
    h_split(v.z, hz, lz); h_split(v.w, hw, lw);
    h01 = pkh(hx, hy); h23 = pkh(hz, hw);
    l01 = pkh(lx, ly); l23 = pkh(lz, lw);
}
__device__ __forceinline__ void mma16h(float* d, const uint32_t* a, const uint32_t* b) {
    asm volatile(
        "mma.sync.aligned.m16n8k16.row.col.f32.f16.f16.f32 "
        "{%0,%1,%2,%3},{%4,%5,%6,%7},{%8,%9},{%0,%1,%2,%3};"
        : "+f"(d[0]), "+f"(d[1]), "+f"(d[2]), "+f"(d[3])
        : "r"(a[0]), "r"(a[1]), "r"(a[2]), "r"(a[3]), "r"(b[0]), "r"(b[1]));
}

// ================= device bodies =================

__device__ void d_prep(int bid, const float* __restrict__ U, const float* __restrict__ hw) {
    float w0 = hw[0], w1 = hw[1], w2 = hw[2], w3 = hw[3];
    float mx = fmaxf(fmaxf(w0, w1), fmaxf(w2, w3));
    float e0 = __expf(w0 - mx), e1 = __expf(w1 - mx), e2 = __expf(w2 - mx), e3 = __expf(w3 - mx);
    float inv = 1.f / (e0 + e1 + e2 + e3);
    float wk[4] = {e0 * inv, e1 * inv, e2 * inv, e3 * inv};
    int t = bid * 256 + threadIdx.x;
    if (t < KH * DDIM * RR) {
        int k = t / (DDIM * RR);
        int d = (t / RR) % DDIM;
        int r = t % RR;
        g_W[(k * RR + r) * DDIM + d] = wk[k] * U[t];
    }
}

__device__ void d_prepT(int bid, const float* __restrict__ U) {
    int t = bid * 256 + threadIdx.x;
    if (t >= CDIM * (DDIM / 2)) return;
    int c = t >> 7, dp = t & 127;
    int k = c >> 4, r = c & 15;
    int d = dp * 2;
    float u0 = U[(k * DDIM + d) * RR + r];
    float u1 = U[(k * DDIM + d + 1) * RR + r];
    __nv_bfloat16 h0, l0, h1, l1;
    bf_split(u0, h0, l0); bf_split(u1, h1, l1);
    g_UtH[t] = pk(h0, h1);
    g_UtL[t] = pk(l0, l1);
}

__device__ void d_hist(int bid, const int* __restrict__ ei, int E) {
    int t = bid * 256 + threadIdx.x;
    if (t < E) atomicAdd(&g_cnt[ei[E + t]], 1);
}

struct SM_M { float s1[16][33]; float s2[16][33]; };

__device__ void d_m1(int bid, const float* __restrict__ A, SM_M* sm) {
    int tid = threadIdx.x;
    int tx = tid & 15, ty = tid >> 4;
    int i0 = (bid >> 3) * 32, j0 = (bid & 7) * 32;
    float c00 = 0, c01 = 0, c10 = 0, c11 = 0;
    for (int t0 = 0; t0 < 256; t0 += 16) {
#pragma unroll
        for (int l = 0; l < 2; l++) {
            int f = tid + l * 256;
            int r = f >> 5, col = f & 31;
            sm->s1[r][col] = A[(t0 + r) * DDIM + i0 + col];
            sm->s2[r][col] = A[(t0 + r) * DDIM + j0 + col];
        }
        __syncthreads();
#pragma unroll
        for (int kk = 0; kk < 16; kk++) {
            float a0 = sm->s1[kk][ty * 2], a1 = sm->s1[kk][ty * 2 + 1];
            float b0 = sm->s2[kk][tx * 2], b1 = sm->s2[kk][tx * 2 + 1];
            c00 += a0 * b0; c01 += a0 * b1; c10 += a1 * b0; c11 += a1 * b1;
        }
        __syncthreads();
    }
    int i = i0 + ty * 2, j = j0 + tx * 2;
    g_M1[i * DDIM + j] = c00;       g_M1[i * DDIM + j + 1] = c01;
    g_M1[(i + 1) * DDIM + j] = c10; g_M1[(i + 1) * DDIM + j + 1] = c11;
}

__device__ void d_m2(int bid, const float* __restrict__ A, SM_M* sm) {
    int tid = threadIdx.x;
    int tx = tid & 15, ty = tid >> 4;
    int i0 = (bid >> 3) * 32, j0 = (bid & 7) * 32;
    float c00 = 0, c01 = 0, c10 = 0, c11 = 0;
    for (int t0 = 0; t0 < 256; t0 += 16) {
#pragma unroll
        for (int l = 0; l < 2; l++) {
            int f = tid + l * 256;
            int tt = f & 15, ii = f >> 4;
            sm->s1[tt][ii] = g_M1[(i0 + ii) * DDIM + t0 + tt];
            int r = f >> 5, col = f & 31;
            sm->s2[r][col] = A[(t0 + r) * DDIM + j0 + col];
        }
        __syncthreads();
#pragma unroll
        for (int kk = 0; kk < 16; kk++) {
            float a0 = sm->s1[kk][ty * 2], a1 = sm->s1[kk][ty * 2 + 1];
            float b0 = sm->s2[kk][tx * 2], b1 = sm->s2[kk][tx * 2 + 1];
            c00 += a0 * b0; c01 += a0 * b1; c10 += a1 * b0; c11 += a1 * b1;
        }
        __syncthreads();
    }
    int i = i0 + ty * 2, j = j0 + tx * 2;
    float mm[2][2];
    mm[0][0] = ((i == j)         ? 1.f : 0.f) + 0.5f * (A[i * DDIM + j]           - c00);
    mm[0][1] = ((i == j + 1)     ? 1.f : 0.f) + 0.5f * (A[i * DDIM + j + 1]       - c01);
    mm[1][0] = ((i + 1 == j)     ? 1.f : 0.f) + 0.5f * (A[(i + 1) * DDIM + j]     - c10);
    mm[1][1] = ((i + 1 == j + 1) ? 1.f : 0.f) + 0.5f * (A[(i + 1) * DDIM + j + 1] - c11);
#pragma unroll
    for (int a = 0; a < 2; a++)
#pragma unroll
        for (int b = 0; b < 2; b++)
            g_M[(i + a) * DDIM + j + b] = mm[a][b];
    // Gtop = 0.5*M, transposed [n=j..][k=i..], (i,i+1) fp16 pair
#pragma unroll
    for (int b = 0; b < 2; b++)
        g_GtF[(j + b) * (XDIM / 2) + (i >> 1)] =
            pkh(__float2half(0.5f * mm[0][b]), __float2half(0.5f * mm[1][b]));
}

__device__ void d_wm(int bid, SM_M* sm) {
    int tid = threadIdx.x;
    int tx = tid & 15, ty = tid >> 4;
    int i0 = (bid >> 3) * 32, j0 = (bid & 7) * 32;
    float c00 = 0, c01 = 0, c10 = 0, c11 = 0;
    for (int t0 = 0; t0 < 256; t0 += 16) {
#pragma unroll
        for (int l = 0; l < 2; l++) {
            int f = tid + l * 256;
            int tt = f & 15, ii = f >> 4;
            sm->s1[tt][ii] = g_W[(i0 + ii) * DDIM + t0 + tt];
            int r = f >> 5, col = f & 31;
            sm->s2[r][col] = g_M[(t0 + r) * DDIM + j0 + col];
        }
        __syncthreads();
#pragma unroll
        for (int kk = 0; kk < 16; kk++) {
            float a0 = sm->s1[kk][ty * 2], a1 = sm->s1[kk][ty * 2 + 1];
            float b0 = sm->s2[kk][tx * 2], b1 = sm->s2[kk][tx * 2 + 1];
            c00 += a0 * b0; c01 += a0 * b1; c10 += a1 * b0; c11 += a1 * b1;
        }
        __syncthreads();
    }
    int i = i0 + ty * 2, j = j0 + tx * 2;
    float cc[2][2] = {{c00, c01}, {c10, c11}};
#pragma unroll
    for (int b = 0; b < 2; b++)
        g_GtF[(j + b) * (XDIM / 2) + 128 + (i >> 1)] =
            pkh(__float2half(0.5f * cc[0][b]), __float2half(0.5f * cc[1][b]));
}

__device__ void d_scan1(int b, int* s_warp) {
    int t = threadIdx.x;
    int base = b * 1024 + t * 4;
    int v[4];
#pragma unroll
    for (int i = 0; i < 4; i++) { int idx = base + i; v[i] = (idx < NNODES) ? g_cnt[idx] : 0; }
    int sum = v[0] + v[1] + v[2] + v[3];
    int lane = t & 31, wid = t >> 5;
    int x = sum;
#pragma unroll
    for (int o = 1; o < 32; o <<= 1) { int y = __shfl_up_sync(0xffffffff, x, o); if (lane >= o) x += y; }
    if (lane == 31) s_warp[wid] = x;
    __syncthreads();
    if (wid == 0) {
        int w = (lane < 8) ? s_warp[lane] : 0;
#pragma unroll
        for (int o = 1; o < 8; o <<= 1) { int y = __shfl_up_sync(0xffffffff, w, o); if (lane >= o) w += y; }
        if (lane < 8) s_warp[lane] = w;
    }
    __syncthreads();
    int warppre = (wid > 0) ? s_warp[wid - 1] : 0;
    int run = warppre + x - sum;
#pragma unroll
    for (int i = 0; i < 4; i++) { int idx = base + i; if (idx < NNODES) g_off[idx] = run; run += v[i]; }
    if (t == 255) g_bsum[b] = warppre + x;
}

__device__ void d_scan2(int* sw) {
    int t = threadIdx.x;
    if (t >= 128) { __syncthreads(); __syncthreads(); return; }
    int v = (t < NBLK_SCAN) ? g_bsum[t] : 0;
    int lane = t & 31, wid = t >> 5;
    int x = v;
#pragma unroll
    for (int o = 1; o < 32; o <<= 1) { int y = __shfl_up_sync(0xffffffff, x, o); if (lane >= o) x += y; }
    if (lane == 31) sw[wid] = x;
    __syncthreads();
    if (t == 0) { int a = 0; for (int i = 0; i < 4; i++) { int tmp = sw[i]; sw[i] = a; a += tmp; } }
    __syncthreads();
    if (t < NBLK_SCAN) g_bpre[t] = sw[wid] + x - v;
}

struct SM_ZU {
    uint32_t sAh[128 * 12]; uint32_t sAl[128 * 12];
    uint32_t sBh[64 * 12];  uint32_t sBl[64 * 12];
};

__device__ void d_zu(int zbid, const float* __restrict__ Z, SM_ZU* sm) {
    int tid = threadIdx.x;
    int rowBase = zbid * 128;
    int warp = tid >> 5, lane = tid & 31;
    int Mw = (warp >> 1) * 32, Nw = (warp & 1) * 32;
    int g = lane >> 2, t4 = lane & 3;

    float4 pa[2]; uint2 pbh, pbl;
    {
#pragma unroll
        for (int l = 0; l < 2; l++) {
            int f = tid + l * 256; int r = f >> 2, k4 = f & 3;
            int gr = rowBase + r; if (gr >= NNODES) gr = NNODES - 1;
            pa[l] = *(const float4*)&Z[gr * DDIM + k4 * 4];
        }
        int n = tid >> 2, kk2 = tid & 3;
        pbh = *(const uint2*)&g_UtH[n * (DDIM / 2) + kk2 * 2];
        pbl = *(const uint2*)&g_UtL[n * (DDIM / 2) + kk2 * 2];
    }
    float acc[8][4];
#pragma unroll
    for (int i = 0; i < 8; i++)
#pragma unroll
        for (int j = 0; j < 4; j++) acc[i][j] = 0.f;

    for (int kt = 0; kt < 16; kt++) {
#pragma unroll
        for (int l = 0; l < 2; l++) {
            int f = tid + l * 256; int r = f >> 2, k4 = f & 3;
            uint32_t h01, h23, l01, l23;
            split_pack4(pa[l], h01, h23, l01, l23);
            sm->sAh[r * 12 + k4 * 2] = h01; sm->sAh[r * 12 + k4 * 2 + 1] = h23;
            sm->sAl[r * 12 + k4 * 2] = l01; sm->sAl[r * 12 + k4 * 2 + 1] = l23;
        }
        {
            int n = tid >> 2, kk2 = tid & 3;
            *(uint2*)&sm->sBh[n * 12 + kk2 * 2] = pbh;
            *(uint2*)&sm->sBl[n * 12 + kk2 * 2] = pbl;
        }
        __syncthreads();
        if (kt < 15) {
            int k0 = (kt + 1) * 16;
#pragma unroll
            for (int l = 0; l < 2; l++) {
                int f = tid + l * 256; int r = f >> 2, k4 = f & 3;
                int gr = rowBase + r; if (gr >= NNODES) gr = NNODES - 1;
                pa[l] = *(const float4*)&Z[gr * DDIM + k0 + k4 * 4];
            }
            int n = tid >> 2, kk2 = tid & 3;
            pbh = *(const uint2*)&g_UtH[n * (DDIM / 2) + k0 / 2 + kk2 * 2];
            pbl = *(const uint2*)&g_UtL[n * (DDIM / 2) + k0 / 2 + kk2 * 2];
        }
        uint32_t Ah[2][4], Al[2][4], Bh[4][2], Bl[4][2];
#pragma unroll
        for (int mt = 0; mt < 2; mt++) {
            int r0 = Mw + mt * 16 + g;
            Ah[mt][0] = sm->sAh[r0 * 12 + t4];       Ah[mt][1] = sm->sAh[(r0 + 8) * 12 + t4];
            Ah[mt][2] = sm->sAh[r0 * 12 + 4 + t4];   Ah[mt][3] = sm->sAh[(r0 + 8) * 12 + 4 + t4];
            Al[mt][0] = sm->sAl[r0 * 12 + t4];       Al[mt][1] = sm->sAl[(r0 + 8) * 12 + t4];
            Al[mt][2] = sm->sAl[r0 * 12 + 4 + t4];   Al[mt][3] = sm->sAl[(r0 + 8) * 12 + 4 + t4];
        }
#pragma unroll
        for (int nt = 0; nt < 4; nt++) {
            int c0 = Nw + nt * 8 + g;
            Bh[nt][0] = sm->sBh[c0 * 12 + t4];  Bh[nt][1] = sm->sBh[c0 * 12 + 4 + t4];
            Bl[nt][0] = sm->sBl[c0 * 12 + t4];  Bl[nt][1] = sm->sBl[c0 * 12 + 4 + t4];
        }
#pragma unroll
        for (int mt = 0; mt < 2; mt++)
#pragma unroll
            for (int nt = 0; nt < 4; nt++) {
                float* d = acc[mt * 4 + nt];
                mma16(d, Ah[mt], Bh[nt]);
                mma16(d, Ah[mt], Bl[nt]);
                mma16(d, Al[mt], Bh[nt]);
            }
        __syncthreads();
    }
#pragma unroll
    for (int mt = 0; mt < 2; mt++)
#pragma unroll
        for (int nt = 0; nt < 4; nt++) {
            int gr0 = rowBase + Mw + mt * 16 + g;
            int c = Nw + nt * 8 + 2 * t4;
            float* d = acc[mt * 4 + nt];
            if (gr0 < NNODES)     *(float2*)&g_ZU[gr0 * CDIM + c]       = make_float2(d[0], d[1]);
            if (gr0 + 8 < NNODES) *(float2*)&g_ZU[(gr0 + 8) * CDIM + c] = make_float2(d[2], d[3]);
        }
}

// ================= merged kernels =================

__global__ void k0() {
    int t = blockIdx.x * 256 + threadIdx.x;
    if (t < NNODES) g_cnt[t] = 0;
}

// k1: m1 | prep | prepT | hist   (m1 only needs Dmat — fully independent)
__global__ void k1(const float* __restrict__ U, const float* __restrict__ hw,
                   const float* __restrict__ Dmat, const int* __restrict__ ei, int E) {
    __shared__ SM_M smM;
    int b = blockIdx.x;
    if (b < 64)       d_m1(b, Dmat, &smM);
    else if (b < 128) d_prep(b - 64, U, hw);
    else if (b < 160) d_prepT(b - 128, U);
    else              d_hist(b - 160, ei, E);
}

// k2: m2 | scan1 | zu
__global__ void k2(const float* __restrict__ Z, const float* __restrict__ A) {
    __shared__ SM_M smM;
    __shared__ int s_warp[8];
    __shared__ SM_ZU smZ;
    int b = blockIdx.x;
    if (b < 64)        d_m2(b, A, &smM);
    else if (b < 162)  d_scan1(b - 64, s_warp);
    else               d_zu(b - 162, Z, &smZ);
}

// k3: wm | scan2
__global__ void k3() {
    __shared__ SM_M smM;
    __shared__ int sw[4];
    int b = blockIdx.x;
    if (b < 16) d_wm(b, &smM);
    else        d_scan2(sw);
}

// k4: scan3
__global__ void k4(int E) {
    int t = blockIdx.x * 256 + threadIdx.x;
    if (t < NNODES) {
        int o = g_off[t] + g_bpre[t >> 10];
        g_off[t] = o;
        g_cursor[t] = o;
    }
    if (t == 0) g_off[NNODES] = E;
}

__global__ void k5(const int* __restrict__ ei, int E) {
    int t = blockIdx.x * 256 + threadIdx.x;
    if (t < E) {
        int dst = ei[E + t];
        int pos = atomicAdd(&g_cursor[dst], 1);
        g_srcl[pos] = ei[t];
    }
}

// ---- agg: warp per node, 4-edge unroll ----
__global__ void k6() {
    int warp = (blockIdx.x * blockDim.x + threadIdx.x) >> 5;
    if (warp >= NNODES) return;
    int l = threadIdx.x & 31;
    float2 zd = *(const float2*)&g_ZU[warp * CDIM + l * 2];
    float ax = 0.f, ay = 0.f, ss = 0.f;
    int i = g_off[warp], end = g_off[warp + 1];
    for (; i + 3 < end; i += 4) {
        int s0 = g_srcl[i], s1 = g_srcl[i + 1], s2 = g_srcl[i + 2], s3 = g_srcl[i + 3];
        float2 a = *(const float2*)&g_ZU[s0 * CDIM + l * 2];
        float2 b = *(const float2*)&g_ZU[s1 * CDIM + l * 2];
        float2 c = *(const float2*)&g_ZU[s2 * CDIM + l * 2];
        float2 d = *(const float2*)&g_ZU[s3 * CDIM + l * 2];
        float p0 = a.x * zd.x + a.y * zd.y;
        float p1 = b.x * zd.x + b.y * zd.y;
        float p2 = c.x * zd.x + c.y * zd.y;
        float p3 = d.x * zd.x + d.y * zd.y;
        p0 += __shfl_xor_sync(0xffffffff, p0, 1);  p1 += __shfl_xor_sync(0xffffffff, p1, 1);
        p2 += __shfl_xor_sync(0xffffffff, p2, 1);  p3 += __shfl_xor_sync(0xffffffff, p3, 1);
        p0 += __shfl_xor_sync(0xffffffff, p0, 2);  p1 += __shfl_xor_sync(0xffffffff, p1, 2);
        p2 += __shfl_xor_sync(0xffffffff, p2, 2);  p3 += __shfl_xor_sync(0xffffffff, p3, 2);
        p0 += __shfl_xor_sync(0xffffffff, p0, 4);  p1 += __shfl_xor_sync(0xffffffff, p1, 4);
        p2 += __shfl_xor_sync(0xffffffff, p2, 4);  p3 += __shfl_xor_sync(0xffffffff, p3, 4);
        float e0 = __expf(p0 * 0.25f), e1 = __expf(p1 * 0.25f);
        float e2 = __expf(p2 * 0.25f), e3 = __expf(p3 * 0.25f);
        ss += (e0 + e1) + (e2 + e3);
        ax += e0 * a.x + e1 * b.x + e2 * c.x + e3 * d.x;
        ay += e0 * a.y + e1 * b.y + e2 * c.y + e3 * d.y;
    }
    for (; i < end; i++) {
        int s0 = g_srcl[i];
        float2 a = *(const float2*)&g_ZU[s0 * CDIM + l * 2];
        float p0 = a.x * zd.x + a.y * zd.y;
        p0 += __shfl_xor_sync(0xffffffff, p0, 1);
        p0 += __shfl_xor_sync(0xffffffff, p0, 2);
        p0 += __shfl_xor_sync(0xffffffff, p0, 4);
        float e0 = __expf(p0 * 0.25f);
        ss += e0; ax += e0 * a.x; ay += e0 * a.y;
    }
    float inv = 1.f / (ss + 1e-16f);
    *(float2*)&g_agg[warp * CDIM + l * 2] = make_float2(ax * inv, ay * inv);
}

// ======== final GEMM: out = relu([Z|Agg] @ G - 0.05), fp16 2-term (A exact, B fp16) ========
__global__ __launch_bounds__(256, 1) void k_final(const float* __restrict__ Z, float* __restrict__ out) {
    __shared__ uint32_t sAh[128 * 12], sAl[128 * 12];
    __shared__ uint32_t sB[128 * 12];
    int tid = threadIdx.x;
    int rowBase = blockIdx.x * 128;
    int colBase = blockIdx.y * 128;
    int warp = tid >> 5, lane = tid & 31;
    int Mw = (warp >> 2) * 64, Nw = (warp & 3) * 32;
    int g = lane >> 2, t4 = lane & 3;

    float4 pa[2]; uint2 pb[2];
    {
#pragma unroll
        for (int l = 0; l < 2; l++) {
            int f = tid + l * 256; int r = f >> 2, k4 = f & 3;
            int gr = rowBase + r; if (gr >= NNODES) gr = NNODES - 1;
            pa[l] = *(const float4*)&Z[gr * DDIM + k4 * 4];
        }
#pragma unroll
        for (int l = 0; l < 2; l++) {
            int f = tid + l * 256; int n = f >> 2, kk2 = f & 3;
            pb[l] = *(const uint2*)&g_GtF[(colBase + n) * (XDIM / 2) + kk2 * 2];
        }
    }
    float acc[16][4];
#pragma unroll
    for (int i = 0; i < 16; i++)
#pragma unroll
        for (int j = 0; j < 4; j++) acc[i][j] = 0.f;

    for (int kt = 0; kt < 20; kt++) {
#pragma unroll
        for (int l = 0; l < 2; l++) {
            int f = tid + l * 256; int r = f >> 2, k4 = f & 3;
            uint32_t h01, h23, l01, l23;
            split_pack4h(pa[l], h01, h23, l01, l23);
            sAh[r * 12 + k4 * 2] = h01; sAh[r * 12 + k4 * 2 + 1] = h23;
            sAl[r * 12 + k4 * 2] = l01; sAl[r * 12 + k4 * 2 + 1] = l23;
        }
#pragma unroll
        for (int l = 0; l < 2; l++) {
            int f = tid + l * 256; int n = f >> 2, kk2 = f & 3;
            *(uint2*)&sB[n * 12 + kk2 * 2] = pb[l];
        }
        __syncthreads();
        if (kt < 19) {
            int kn = kt + 1;
            const float* Aptr; int ld, koff;
            if (kn < 16) { Aptr = Z;     ld = DDIM; koff = kn * 16; }
            else         { Aptr = g_agg; ld = CDIM; koff = kn * 16 - DDIM; }
#pragma unroll
            for (int l = 0; l < 2; l++) {
                int f = tid + l * 256; int r = f >> 2, k4 = f & 3;
                int gr = rowBase + r; if (gr >= NNODES) gr = NNODES - 1;
                pa[l] = *(const float4*)&Aptr[gr * ld + koff + k4 * 4];
            }
#pragma unroll
            for (int l = 0; l < 2; l++) {
                int f = tid + l * 256; int n = f >> 2, kk2 = f & 3;
                pb[l] = *(const uint2*)&g_GtF[(colBase + n) * (XDIM / 2) + kn * 8 + kk2 * 2];
            }
        }
        uint32_t Ah[4][4], Al[4][4], Bf[4][2];
#pragma unroll
        for (int mt = 0; mt < 4; mt++) {
            int r0 = Mw + mt * 16 + g;
            Ah[mt][0] = sAh[r0 * 12 + t4];       Ah[mt][1] = sAh[(r0 + 8) * 12 + t4];
            Ah[mt][2] = sAh[r0 * 12 + 4 + t4];   Ah[mt][3] = sAh[(r0 + 8) * 12 + 4 + t4];
            Al[mt][0] = sAl[r0 * 12 + t4];       Al[mt][1] = sAl[(r0 + 8) * 12 + t4];
            Al[mt][2] = sAl[r0 * 12 + 4 + t4];   Al[mt][3] = sAl[(r0 + 8) * 12 + 4 + t4];
        }
#pragma unroll
        for (int nt = 0; nt < 4; nt++) {
            int c0 = Nw + nt * 8 + g;
            Bf[nt][0] = sB[c0 * 12 + t4];  Bf[nt][1] = sB[c0 * 12 + 4 + t4];
        }
#pragma unroll
        for (int mt = 0; mt < 4; mt++)
#pragma unroll
            for (int nt = 0; nt < 4; nt++) {
                float* d = acc[mt * 4 + nt];
                mma16h(d, Ah[mt], Bf[nt]);
                mma16h(d, Al[mt], Bf[nt]);
            }
        __syncthreads();
    }
#pragma unroll
    for (int mt = 0; mt < 4; mt++)
#pragma unroll
        for (int nt = 0; nt < 4; nt++) {
            int gr0 = rowBase + Mw + mt * 16 + g;
            int c = colBase + Nw + nt * 8 + 2 * t4;
            float* d = acc[mt * 4 + nt];
            if (gr0 < NNODES)
                *(float2*)&out[gr0 * DDIM + c] =
                    make_float2(fmaxf(d[0] - 0.05f, 0.f), fmaxf(d[1] - 0.05f, 0.f));
            if (gr0 + 8 < NNODES)
                *(float2*)&out[(gr0 + 8) * DDIM + c] =
                    make_float2(fmaxf(d[2] - 0.05f, 0.f), fmaxf(d[3] - 0.05f, 0.f));
        }
}

extern "C" void kernel_launch(void* const* d_in, const int* in_sizes, int n_in,
                              void* d_out, int out_size) {
    const float* Z    = (const float*)d_in[0];
    const float* U    = (const float*)d_in[1];
    const float* Dmat = (const float*)d_in[2];
    const float* hw   = (const float*)d_in[3];
    const int*   ei   = (const int*)d_in[4];
    int E = in_sizes[4] / 2;
    float* out = (float*)d_out;

    int histBlocks = (E + 255) / 256;
    k0<<<(NNODES + 255) / 256, 256>>>();                     // zero counts
    k1<<<160 + histBlocks, 256>>>(U, hw, Dmat, ei, E);       // m1 | prep | prepT | hist
    k2<<<162 + (NNODES + 127) / 128, 256>>>(Z, Dmat);        // m2 | scan1 | zu
    k3<<<17, 256>>>();                                       // wm | scan2
    k4<<<(NNODES + 255) / 256, 256>>>(E);                    // scan3
    k5<<<histBlocks, 256>>>(ei, E);                          // scatter
    k6<<<(NNODES * 32 + 255) / 256, 256>>>();                // agg
    k_final<<<dim3((NNODES + 127) / 128, DDIM / 128), 256>>>(Z, out);
}

// round 17
// speedup vs baseline: 1.1735x; 1.1735x over previous
#include <cuda_runtime.h>
#include <cuda_bf16.h>
#include <cstdint>

#define NNODES 100000
#define DDIM 256
#define KH 4
#define RR 16
#define CDIM 64            // KH*RR
#define XDIM (DDIM + CDIM) // 320
#define EMAX 1700000
#define NBLK_SCAN 98       // ceil(NNODES/1024)

// -------- scratch --------
__device__ float g_ZU[NNODES * CDIM];
__device__ float g_agg[NNODES * CDIM];
__device__ float g_W[CDIM * DDIM];
__device__ float g_M1[DDIM * DDIM];
__device__ float g_M[DDIM * DDIM];
__device__ uint32_t g_UtH[CDIM * (DDIM / 2)];   // bf16 pairs (zu)
__device__ uint32_t g_UtL[CDIM * (DDIM / 2)];
__device__ uint32_t g_GtH[DDIM * (XDIM / 2)];   // bf16 pairs [n][k-pair] (final)
__device__ uint32_t g_GtL[DDIM * (XDIM / 2)];
// CSR
__device__ int g_cnt[NNODES];
__device__ int g_off[NNODES + 1];
__device__ int g_cursor[NNODES];
__device__ int g_bsum[NBLK_SCAN];
__device__ int g_bpre[NBLK_SCAN];
__device__ int g_srcl[EMAX];

// -------- bf16 helpers --------
__device__ __forceinline__ uint32_t pk(__nv_bfloat16 a, __nv_bfloat16 b) {
    __nv_bfloat162 t = __halves2bfloat162(a, b);
    return *(uint32_t*)&t;
}
__device__ __forceinline__ void bf_split(float x, __nv_bfloat16& h, __nv_bfloat16& l) {
    h = __float2bfloat16(x);
    l = __float2bfloat16(x - __bfloat162float(h));
}
__device__ __forceinline__ void split_pack4(float4 v, uint32_t& h01, uint32_t& h23,
                                            uint32_t& l01, uint32_t& l23) {
    __nv_bfloat16 hx, lx, hy, ly, hz, lz, hw, lw;
    bf_split(v.x, hx, lx); bf_split(v.y, hy, ly);
    bf_split(v.z, hz, lz); bf_split(v.w, hw, lw);
    h01 = pk(hx, hy); h23 = pk(hz, hw);
    l01 = pk(lx, ly); l23 = pk(lz, lw);
}
__device__ __forceinline__ void mma16(float* d, const uint32_t* a, const uint32_t* b) {
    asm volatile(
        "mma.sync.aligned.m16n8k16.row.col.f32.bf16.bf16.f32 "
        "{%0,%1,%2,%3},{%4,%5,%6,%7},{%8,%9},{%0,%1,%2,%3};"
        : "+f"(d[0]), "+f"(d[1]), "+f"(d[2]), "+f"(d[3])
        : "r"(a[0]), "r"(a[1]), "r"(a[2]), "r"(a[3]), "r"(b[0]), "r"(b[1]));
}

// ================= device bodies =================

__device__ void d_prep(int bid, const float* __restrict__ U, const float* __restrict__ hw) {
    float w0 = hw[0], w1 = hw[1], w2 = hw[2], w3 = hw[3];
    float mx = fmaxf(fmaxf(w0, w1), fmaxf(w2, w3));
    float e0 = __expf(w0 - mx), e1 = __expf(w1 - mx), e2 = __expf(w2 - mx), e3 = __expf(w3 - mx);
    float inv = 1.f / (e0 + e1 + e2 + e3);
    float wk[4] = {e0 * inv, e1 * inv, e2 * inv, e3 * inv};
    int t = bid * 256 + threadIdx.x;
    if (t < KH * DDIM * RR) {
        int k = t / (DDIM * RR);
        int d = (t / RR) % DDIM;
        int r = t % RR;
        g_W[(k * RR + r) * DDIM + d] = wk[k] * U[t];
    }
}

__device__ void d_prepT(int bid, const float* __restrict__ U) {
    int t = bid * 256 + threadIdx.x;
    if (t >= CDIM * (DDIM / 2)) return;
    int c = t >> 7, dp = t & 127;
    int k = c >> 4, r = c & 15;
    int d = dp * 2;
    float u0 = U[(k * DDIM + d) * RR + r];
    float u1 = U[(k * DDIM + d + 1) * RR + r];
    __nv_bfloat16 h0, l0, h1, l1;
    bf_split(u0, h0, l0); bf_split(u1, h1, l1);
    g_UtH[t] = pk(h0, h1);
    g_UtL[t] = pk(l0, l1);
}

__device__ void d_hist(int bid, const int* __restrict__ ei, int E) {
    int t = bid * 256 + threadIdx.x;
    if (t < E) atomicAdd(&g_cnt[ei[E + t]], 1);
}

struct SM_M { float s1[16][33]; float s2[16][33]; };

__device__ void d_m1(int bid, const float* __restrict__ A, SM_M* sm) {
    int tid = threadIdx.x;
    int tx = tid & 15, ty = tid >> 4;
    int i0 = (bid >> 3) * 32, j0 = (bid & 7) * 32;
    float c00 = 0, c01 = 0, c10 = 0, c11 = 0;
    for (int t0 = 0; t0 < 256; t0 += 16) {
#pragma unroll
        for (int l = 0; l < 2; l++) {
            int f = tid + l * 256;
            int r = f >> 5, col = f & 31;
            sm->s1[r][col] = A[(t0 + r) * DDIM + i0 + col];
            sm->s2[r][col] = A[(t0 + r) * DDIM + j0 + col];
        }
        __syncthreads();
#pragma unroll
        for (int kk = 0; kk < 16; kk++) {
            float a0 = sm->s1[kk][ty * 2], a1 = sm->s1[kk][ty * 2 + 1];
            float b0 = sm->s2[kk][tx * 2], b1 = sm->s2[kk][tx * 2 + 1];
            c00 += a0 * b0; c01 += a0 * b1; c10 += a1 * b0; c11 += a1 * b1;
        }
        __syncthreads();
    }
    int i = i0 + ty * 2, j = j0 + tx * 2;
    g_M1[i * DDIM + j] = c00;       g_M1[i * DDIM + j + 1] = c01;
    g_M1[(i + 1) * DDIM + j] = c10; g_M1[(i + 1) * DDIM + j + 1] = c11;
}

__device__ void d_m2(int bid, const float* __restrict__ A, SM_M* sm) {
    int tid = threadIdx.x;
    int tx = tid & 15, ty = tid >> 4;
    int i0 = (bid >> 3) * 32, j0 = (bid & 7) * 32;
    float c00 = 0, c01 = 0, c10 = 0, c11 = 0;
    for (int t0 = 0; t0 < 256; t0 += 16) {
#pragma unroll
        for (int l = 0; l < 2; l++) {
            int f = tid + l * 256;
            int tt = f & 15, ii = f >> 4;
            sm->s1[tt][ii] = g_M1[(i0 + ii) * DDIM + t0 + tt];
            int r = f >> 5, col = f & 31;
            sm->s2[r][col] = A[(t0 + r) * DDIM + j0 + col];
        }
        __syncthreads();
#pragma unroll
        for (int kk = 0; kk < 16; kk++) {
            float a0 = sm->s1[kk][ty * 2], a1 = sm->s1[kk][ty * 2 + 1];
            float b0 = sm->s2[kk][tx * 2], b1 = sm->s2[kk][tx * 2 + 1];
            c00 += a0 * b0; c01 += a0 * b1; c10 += a1 * b0; c11 += a1 * b1;
        }
        __syncthreads();
    }
    int i = i0 + ty * 2, j = j0 + tx * 2;
    float mm[2][2];
    mm[0][0] = ((i == j)         ? 1.f : 0.f) + 0.5f * (A[i * DDIM + j]           - c00);
    mm[0][1] = ((i == j + 1)     ? 1.f : 0.f) + 0.5f * (A[i * DDIM + j + 1]       - c01);
    mm[1][0] = ((i + 1 == j)     ? 1.f : 0.f) + 0.5f * (A[(i + 1) * DDIM + j]     - c10);
    mm[1][1] = ((i + 1 == j + 1) ? 1.f : 0.f) + 0.5f * (A[(i + 1) * DDIM + j + 1] - c11);
#pragma unroll
    for (int a = 0; a < 2; a++)
#pragma unroll
        for (int b = 0; b < 2; b++)
            g_M[(i + a) * DDIM + j + b] = mm[a][b];
    // Gtop = 0.5*M, transposed [n=j][k=i], (i,i+1) bf16 pair (hi/lo)
    __nv_bfloat16 h0, l0, h1, l1;
#pragma unroll
    for (int b = 0; b < 2; b++) {
        bf_split(0.5f * mm[0][b], h0, l0); bf_split(0.5f * mm[1][b], h1, l1);
        g_GtH[(j + b) * (XDIM / 2) + (i >> 1)] = pk(h0, h1);
        g_GtL[(j + b) * (XDIM / 2) + (i >> 1)] = pk(l0, l1);
    }
}

__device__ void d_wm(int bid, SM_M* sm) {
    int tid = threadIdx.x;
    int tx = tid & 15, ty = tid >> 4;
    int i0 = (bid >> 3) * 32, j0 = (bid & 7) * 32;
    float c00 = 0, c01 = 0, c10 = 0, c11 = 0;
    for (int t0 = 0; t0 < 256; t0 += 16) {
#pragma unroll
        for (int l = 0; l < 2; l++) {
            int f = tid + l * 256;
            int tt = f & 15, ii = f >> 4;
            sm->s1[tt][ii] = g_W[(i0 + ii) * DDIM + t0 + tt];
            int r = f >> 5, col = f & 31;
            sm->s2[r][col] = g_M[(t0 + r) * DDIM + j0 + col];
        }
        __syncthreads();
#pragma unroll
        for (int kk = 0; kk < 16; kk++) {
            float a0 = sm->s1[kk][ty * 2], a1 = sm->s1[kk][ty * 2 + 1];
            float b0 = sm->s2[kk][tx * 2], b1 = sm->s2[kk][tx * 2 + 1];
            c00 += a0 * b0; c01 += a0 * b1; c10 += a1 * b0; c11 += a1 * b1;
        }
        __syncthreads();
    }
    int i = i0 + ty * 2, j = j0 + tx * 2;
    float cc[2][2] = {{c00, c01}, {c10, c11}};
    __nv_bfloat16 h0, l0, h1, l1;
#pragma unroll
    for (int b = 0; b < 2; b++) {
        bf_split(0.5f * cc[0][b], h0, l0); bf_split(0.5f * cc[1][b], h1, l1);
        g_GtH[(j + b) * (XDIM / 2) + 128 + (i >> 1)] = pk(h0, h1);
        g_GtL[(j + b) * (XDIM / 2) + 128 + (i >> 1)] = pk(l0, l1);
    }
}

__device__ void d_scan1(int b, int* s_warp) {
    int t = threadIdx.x;
    int base = b * 1024 + t * 4;
    int v[4];
#pragma unroll
    for (int i = 0; i < 4; i++) { int idx = base + i; v[i] = (idx < NNODES) ? g_cnt[idx] : 0; }
    int sum = v[0] + v[1] + v[2] + v[3];
    int lane = t & 31, wid = t >> 5;
    int x = sum;
#pragma unroll
    for (int o = 1; o < 32; o <<= 1) { int y = __shfl_up_sync(0xffffffff, x, o); if (lane >= o) x += y; }
    if (lane == 31) s_warp[wid] = x;
    __syncthreads();
    if (wid == 0) {
        int w = (lane < 8) ? s_warp[lane] : 0;
#pragma unroll
        for (int o = 1; o < 8; o <<= 1) { int y = __shfl_up_sync(0xffffffff, w, o); if (lane >= o) w += y; }
        if (lane < 8) s_warp[lane] = w;
    }
    __syncthreads();
    int warppre = (wid > 0) ? s_warp[wid - 1] : 0;
    int run = warppre + x - sum;
#pragma unroll
    for (int i = 0; i < 4; i++) { int idx = base + i; if (idx < NNODES) g_off[idx] = run; run += v[i]; }
    if (t == 255) g_bsum[b] = warppre + x;
}

__device__ void d_scan2(int* sw) {
    int t = threadIdx.x;
    if (t >= 128) { __syncthreads(); __syncthreads(); return; }
    int v = (t < NBLK_SCAN) ? g_bsum[t] : 0;
    int lane = t & 31, wid = t >> 5;
    int x = v;
#pragma unroll
    for (int o = 1; o < 32; o <<= 1) { int y = __shfl_up_sync(0xffffffff, x, o); if (lane >= o) x += y; }
    if (lane == 31) sw[wid] = x;
    __syncthreads();
    if (t == 0) { int a = 0; for (int i = 0; i < 4; i++) { int tmp = sw[i]; sw[i] = a; a += tmp; } }
    __syncthreads();
    if (t < NBLK_SCAN) g_bpre[t] = sw[wid] + x - v;
}

struct SM_ZU {
    uint32_t sAh[128 * 12]; uint32_t sAl[128 * 12];
    uint32_t sBh[64 * 12];  uint32_t sBl[64 * 12];
};

__device__ void d_zu(int zbid, const float* __restrict__ Z, SM_ZU* sm) {
    int tid = threadIdx.x;
    int rowBase = zbid * 128;
    int warp = tid >> 5, lane = tid & 31;
    int Mw = (warp >> 1) * 32, Nw = (warp & 1) * 32;
    int g = lane >> 2, t4 = lane & 3;

    float4 pa[2]; uint2 pbh, pbl;
    {
#pragma unroll
        for (int l = 0; l < 2; l++) {
            int f = tid + l * 256; int r = f >> 2, k4 = f & 3;
            int gr = rowBase + r; if (gr >= NNODES) gr = NNODES - 1;
            pa[l] = *(const float4*)&Z[gr * DDIM + k4 * 4];
        }
        int n = tid >> 2, kk2 = tid & 3;
        pbh = *(const uint2*)&g_UtH[n * (DDIM / 2) + kk2 * 2];
        pbl = *(const uint2*)&g_UtL[n * (DDIM / 2) + kk2 * 2];
    }
    float acc[8][4];
#pragma unroll
    for (int i = 0; i < 8; i++)
#pragma unroll
        for (int j = 0; j < 4; j++) acc[i][j] = 0.f;

    for (int kt = 0; kt < 16; kt++) {
#pragma unroll
        for (int l = 0; l < 2; l++) {
            int f = tid + l * 256; int r = f >> 2, k4 = f & 3;
            uint32_t h01, h23, l01, l23;
            split_pack4(pa[l], h01, h23, l01, l23);
            sm->sAh[r * 12 + k4 * 2] = h01; sm->sAh[r * 12 + k4 * 2 + 1] = h23;
            sm->sAl[r * 12 + k4 * 2] = l01; sm->sAl[r * 12 + k4 * 2 + 1] = l23;
        }
        {
            int n = tid >> 2, kk2 = tid & 3;
            *(uint2*)&sm->sBh[n * 12 + kk2 * 2] = pbh;
            *(uint2*)&sm->sBl[n * 12 + kk2 * 2] = pbl;
        }
        __syncthreads();
        if (kt < 15) {
            int k0 = (kt + 1) * 16;
#pragma unroll
            for (int l = 0; l < 2; l++) {
                int f = tid + l * 256; int r = f >> 2, k4 = f & 3;
                int gr = rowBase + r; if (gr >= NNODES) gr = NNODES - 1;
                pa[l] = *(const float4*)&Z[gr * DDIM + k0 + k4 * 4];
            }
            int n = tid >> 2, kk2 = tid & 3;
            pbh = *(const uint2*)&g_UtH[n * (DDIM / 2) + k0 / 2 + kk2 * 2];
            pbl = *(const uint2*)&g_UtL[n * (DDIM / 2) + k0 / 2 + kk2 * 2];
        }
        uint32_t Ah[2][4], Al[2][4], Bh[4][2], Bl[4][2];
#pragma unroll
        for (int mt = 0; mt < 2; mt++) {
            int r0 = Mw + mt * 16 + g;
            Ah[mt][0] = sm->sAh[r0 * 12 + t4];       Ah[mt][1] = sm->sAh[(r0 + 8) * 12 + t4];
            Ah[mt][2] = sm->sAh[r0 * 12 + 4 + t4];   Ah[mt][3] = sm->sAh[(r0 + 8) * 12 + 4 + t4];
            Al[mt][0] = sm->sAl[r0 * 12 + t4];       Al[mt][1] = sm->sAl[(r0 + 8) * 12 + t4];
            Al[mt][2] = sm->sAl[r0 * 12 + 4 + t4];   Al[mt][3] = sm->sAl[(r0 + 8) * 12 + 4 + t4];
        }
#pragma unroll
        for (int nt = 0; nt < 4; nt++) {
            int c0 = Nw + nt * 8 + g;
            Bh[nt][0] = sm->sBh[c0 * 12 + t4];  Bh[nt][1] = sm->sBh[c0 * 12 + 4 + t4];
            Bl[nt][0] = sm->sBl[c0 * 12 + t4];  Bl[nt][1] = sm->sBl[c0 * 12 + 4 + t4];
        }
#pragma unroll
        for (int mt = 0; mt < 2; mt++)
#pragma unroll
            for (int nt = 0; nt < 4; nt++) {
                float* d = acc[mt * 4 + nt];
                mma16(d, Ah[mt], Bh[nt]);
                mma16(d, Ah[mt], Bl[nt]);
                mma16(d, Al[mt], Bh[nt]);
            }
        __syncthreads();
    }
#pragma unroll
    for (int mt = 0; mt < 2; mt++)
#pragma unroll
        for (int nt = 0; nt < 4; nt++) {
            int gr0 = rowBase + Mw + mt * 16 + g;
            int c = Nw + nt * 8 + 2 * t4;
            float* d = acc[mt * 4 + nt];
            if (gr0 < NNODES)     *(float2*)&g_ZU[gr0 * CDIM + c]       = make_float2(d[0], d[1]);
            if (gr0 + 8 < NNODES) *(float2*)&g_ZU[(gr0 + 8) * CDIM + c] = make_float2(d[2], d[3]);
        }
}

// ================= merged kernels =================

// k1: m1 | prep | prepT | hist
__global__ void k1(const float* __restrict__ U, const float* __restrict__ hw,
                   const float* __restrict__ Dmat, const int* __restrict__ ei, int E) {
    __shared__ SM_M smM;
    int b = blockIdx.x;
    if (b < 64)       d_m1(b, Dmat, &smM);
    else if (b < 128) d_prep(b - 64, U, hw);
    else if (b < 160) d_prepT(b - 128, U);
    else              d_hist(b - 160, ei, E);
}

// k2: m2 | scan1 | zu
__global__ void k2(const float* __restrict__ Z, const float* __restrict__ A) {
    __shared__ SM_M smM;
    __shared__ int s_warp[8];
    __shared__ SM_ZU smZ;
    int b = blockIdx.x;
    if (b < 64)        d_m2(b, A, &smM);
    else if (b < 162)  d_scan1(b - 64, s_warp);
    else               d_zu(b - 162, Z, &smZ);
}

// k3: wm | scan2
__global__ void k3() {
    __shared__ SM_M smM;
    __shared__ int sw[4];
    int b = blockIdx.x;
    if (b < 16) d_wm(b, &smM);
    else        d_scan2(sw);
}

// k4: scan3
__global__ void k4(int E) {
    int t = blockIdx.x * 256 + threadIdx.x;
    if (t < NNODES) {
        int o = g_off[t] + g_bpre[t >> 10];
        g_off[t] = o;
        g_cursor[t] = o;
    }
    if (t == 0) g_off[NNODES] = E;
}

__global__ void k5(const int* __restrict__ ei, int E) {
    int t = blockIdx.x * 256 + threadIdx.x;
    if (t < E) {
        int dst = ei[E + t];
        int pos = atomicAdd(&g_cursor[dst], 1);
        g_srcl[pos] = ei[t];
    }
}

// ---- agg: warp per node, 8-edge unroll (MLP=8) ----
__global__ void k6() {
    int warp = (blockIdx.x * blockDim.x + threadIdx.x) >> 5;
    if (warp >= NNODES) return;
    int l = threadIdx.x & 31;
    float2 zd = *(const float2*)&g_ZU[warp * CDIM + l * 2];
    float ax = 0.f, ay = 0.f, ss = 0.f;
    int i = g_off[warp], end = g_off[warp + 1];
    for (; i + 7 < end; i += 8) {
        int s[8]; float2 v[8]; float p[8];
#pragma unroll
        for (int e = 0; e < 8; e++) s[e] = g_srcl[i + e];
#pragma unroll
        for (int e = 0; e < 8; e++) v[e] = *(const float2*)&g_ZU[s[e] * CDIM + l * 2];
#pragma unroll
        for (int e = 0; e < 8; e++) p[e] = v[e].x * zd.x + v[e].y * zd.y;
#pragma unroll
        for (int o = 1; o < 8; o <<= 1)
#pragma unroll
            for (int e = 0; e < 8; e++) p[e] += __shfl_xor_sync(0xffffffff, p[e], o);
#pragma unroll
        for (int e = 0; e < 8; e++) {
            float ee = __expf(p[e] * 0.25f);
            ss += ee; ax += ee * v[e].x; ay += ee * v[e].y;
        }
    }
    for (; i + 3 < end; i += 4) {
        int s[4]; float2 v[4]; float p[4];
#pragma unroll
        for (int e = 0; e < 4; e++) s[e] = g_srcl[i + e];
#pragma unroll
        for (int e = 0; e < 4; e++) v[e] = *(const float2*)&g_ZU[s[e] * CDIM + l * 2];
#pragma unroll
        for (int e = 0; e < 4; e++) p[e] = v[e].x * zd.x + v[e].y * zd.y;
#pragma unroll
        for (int o = 1; o < 8; o <<= 1)
#pragma unroll
            for (int e = 0; e < 4; e++) p[e] += __shfl_xor_sync(0xffffffff, p[e], o);
#pragma unroll
        for (int e = 0; e < 4; e++) {
            float ee = __expf(p[e] * 0.25f);
            ss += ee; ax += ee * v[e].x; ay += ee * v[e].y;
        }
    }
    for (; i < end; i++) {
        int s0 = g_srcl[i];
        float2 a = *(const float2*)&g_ZU[s0 * CDIM + l * 2];
        float p0 = a.x * zd.x + a.y * zd.y;
        p0 += __shfl_xor_sync(0xffffffff, p0, 1);
        p0 += __shfl_xor_sync(0xffffffff, p0, 2);
        p0 += __shfl_xor_sync(0xffffffff, p0, 4);
        float e0 = __expf(p0 * 0.25f);
        ss += e0; ax += e0 * a.x; ay += e0 * a.y;
    }
    float inv = 1.f / (ss + 1e-16f);
    *(float2*)&g_agg[warp * CDIM + l * 2] = make_float2(ax * inv, ay * inv);
}

// ======== final GEMM: out = relu([Z|Agg] @ G - 0.05) via bf16 3-term mma ========
__global__ __launch_bounds__(256, 1) void k_final(const float* __restrict__ Z, float* __restrict__ out) {
    __shared__ uint32_t sAh[128 * 12], sAl[128 * 12];
    __shared__ uint32_t sBh[128 * 12], sBl[128 * 12];
    int tid = threadIdx.x;
    int rowBase = blockIdx.x * 128;
    int colBase = blockIdx.y * 128;
    int warp = tid >> 5, lane = tid & 31;
    int Mw = (warp >> 2) * 64, Nw = (warp & 3) * 32;
    int g = lane >> 2, t4 = lane & 3;

    float4 pa[2]; uint2 pbh[2], pbl[2];
    {
#pragma unroll
        for (int l = 0; l < 2; l++) {
            int f = tid + l * 256; int r = f >> 2, k4 = f & 3;
            int gr = rowBase + r; if (gr >= NNODES) gr = NNODES - 1;
            pa[l] = *(const float4*)&Z[gr * DDIM + k4 * 4];
        }
#pragma unroll
        for (int l = 0; l < 2; l++) {
            int f = tid + l * 256; int n = f >> 2, kk2 = f & 3;
            pbh[l] = *(const uint2*)&g_GtH[(colBase + n) * (XDIM / 2) + kk2 * 2];
            pbl[l] = *(const uint2*)&g_GtL[(colBase + n) * (XDIM / 2) + kk2 * 2];
        }
    }
    float acc[16][4];
#pragma unroll
    for (int i = 0; i < 16; i++)
#pragma unroll
        for (int j = 0; j < 4; j++) acc[i][j] = 0.f;

    for (int kt = 0; kt < 20; kt++) {
#pragma unroll
        for (int l = 0; l < 2; l++) {
            int f = tid + l * 256; int r = f >> 2, k4 = f & 3;
            uint32_t h01, h23, l01, l23;
            split_pack4(pa[l], h01, h23, l01, l23);
            sAh[r * 12 + k4 * 2] = h01; sAh[r * 12 + k4 * 2 + 1] = h23;
            sAl[r * 12 + k4 * 2] = l01; sAl[r * 12 + k4 * 2 + 1] = l23;
        }
#pragma unroll
        for (int l = 0; l < 2; l++) {
            int f = tid + l * 256; int n = f >> 2, kk2 = f & 3;
            *(uint2*)&sBh[n * 12 + kk2 * 2] = pbh[l];
            *(uint2*)&sBl[n * 12 + kk2 * 2] = pbl[l];
        }
        __syncthreads();
        if (kt < 19) {
            int kn = kt + 1;
            const float* Aptr; int ld, koff;
            if (kn < 16) { Aptr = Z;     ld = DDIM; koff = kn * 16; }
            else         { Aptr = g_agg; ld = CDIM; koff = kn * 16 - DDIM; }
#pragma unroll
            for (int l = 0; l < 2; l++) {
                int f = tid + l * 256; int r = f >> 2, k4 = f & 3;
                int gr = rowBase + r; if (gr >= NNODES) gr = NNODES - 1;
                pa[l] = *(const float4*)&Aptr[gr * ld + koff + k4 * 4];
            }
#pragma unroll
            for (int l = 0; l < 2; l++) {
                int f = tid + l * 256; int n = f >> 2, kk2 = f & 3;
                pbh[l] = *(const uint2*)&g_GtH[(colBase + n) * (XDIM / 2) + kn * 8 + kk2 * 2];
                pbl[l] = *(const uint2*)&g_GtL[(colBase + n) * (XDIM / 2) + kn * 8 + kk2 * 2];
            }
        }
        uint32_t Ah[4][4], Al[4][4], Bh[4][2], Bl[4][2];
#pragma unroll
        for (int mt = 0; mt < 4; mt++) {
            int r0 = Mw + mt * 16 + g;
            Ah[mt][0] = sAh[r0 * 12 + t4];       Ah[mt][1] = sAh[(r0 + 8) * 12 + t4];
            Ah[mt][2] = sAh[r0 * 12 + 4 + t4];   Ah[mt][3] = sAh[(r0 + 8) * 12 + 4 + t4];
            Al[mt][0] = sAl[r0 * 12 + t4];       Al[mt][1] = sAl[(r0 + 8) * 12 + t4];
            Al[mt][2] = sAl[r0 * 12 + 4 + t4];   Al[mt][3] = sAl[(r0 + 8) * 12 + 4 + t4];
        }
#pragma unroll
        for (int nt = 0; nt < 4; nt++) {
            int c0 = Nw + nt * 8 + g;
            Bh[nt][0] = sBh[c0 * 12 + t4];  Bh[nt][1] = sBh[c0 * 12 + 4 + t4];
            Bl[nt][0] = sBl[c0 * 12 + t4];  Bl[nt][1] = sBl[c0 * 12 + 4 + t4];
        }
#pragma unroll
        for (int mt = 0; mt < 4; mt++)
#pragma unroll
            for (int nt = 0; nt < 4; nt++) {
                float* d = acc[mt * 4 + nt];
                mma16(d, Ah[mt], Bh[nt]);
                mma16(d, Ah[mt], Bl[nt]);
                mma16(d, Al[mt], Bh[nt]);
            }
        __syncthreads();
    }
#pragma unroll
    for (int mt = 0; mt < 4; mt++)
#pragma unroll
        for (int nt = 0; nt < 4; nt++) {
            int gr0 = rowBase + Mw + mt * 16 + g;
            int c = colBase + Nw + nt * 8 + 2 * t4;
            float* d = acc[mt * 4 + nt];
            if (gr0 < NNODES)
                *(float2*)&out[gr0 * DDIM + c] =
                    make_float2(fmaxf(d[0] - 0.05f, 0.f), fmaxf(d[1] - 0.05f, 0.f));
            if (gr0 + 8 < NNODES)
                *(float2*)&out[(gr0 + 8) * DDIM + c] =
                    make_float2(fmaxf(d[2] - 0.05f, 0.f), fmaxf(d[3] - 0.05f, 0.f));
        }
}

extern "C" void kernel_launch(void* const* d_in, const int* in_sizes, int n_in,
                              void* d_out, int out_size) {
    const float* Z    = (const float*)d_in[0];
    const float* U    = (const float*)d_in[1];
    const float* Dmat = (const float*)d_in[2];
    const float* hw   = (const float*)d_in[3];
    const int*   ei   = (const int*)d_in[4];
    int E = in_sizes[4] / 2;
    float* out = (float*)d_out;

    // zero degree counts via memset node (replaces k0 kernel)
    void* cntPtr = nullptr;
    cudaGetSymbolAddress(&cntPtr, g_cnt);
    cudaMemsetAsync(cntPtr, 0, NNODES * sizeof(int));

    int histBlocks = (E + 255) / 256;
    k1<<<160 + histBlocks, 256>>>(U, hw, Dmat, ei, E);       // m1 | prep | prepT | hist
    k2<<<162 + (NNODES + 127) / 128, 256>>>(Z, Dmat);        // m2 | scan1 | zu
    k3<<<17, 256>>>();                                       // wm | scan2
    k4<<<(NNODES + 255) / 256, 256>>>(E);                    // scan3
    k5<<<histBlocks, 256>>>(ei, E);                          // scatter
    k6<<<(NNODES * 32 + 255) / 256, 256>>>();                // agg (8-edge unroll)
    k_final<<<dim3((NNODES + 127) / 128, DDIM / 128), 256>>>(Z, out);
}